// round 1
// baseline (speedup 1.0000x reference)
#include <cuda_runtime.h>
#include <math_constants.h>

// Problem shape (fixed by the dataset)
#define BATCH 8
#define CHANS 3
#define IMG_H 720
#define IMG_W 1280
#define EPS_F 1e-6f
// log2(1.414) computed in double precision
#define LOG2_WARP_BASE 0.49978212546913446f

__device__ int g_min_bits;

__global__ void init_min_kernel() {
    g_min_bits = __float_as_int(CUDART_INF_F);
}

// Grid-stride min reduction over disp (float4 vectorized).
__global__ void min_reduce_kernel(const float* __restrict__ disp, int n4) {
    float m = CUDART_INF_F;
    const float4* d4 = (const float4*)disp;
    for (int i = blockIdx.x * blockDim.x + threadIdx.x; i < n4;
         i += gridDim.x * blockDim.x) {
        float4 v = d4[i];
        m = fminf(m, fminf(fminf(v.x, v.y), fminf(v.z, v.w)));
    }
    // warp reduce
    #pragma unroll
    for (int off = 16; off > 0; off >>= 1)
        m = fminf(m, __shfl_xor_sync(0xFFFFFFFF, m, off));
    __shared__ float s_min[8];
    int wid = threadIdx.x >> 5;
    int lid = threadIdx.x & 31;
    if (lid == 0) s_min[wid] = m;
    __syncthreads();
    if (threadIdx.x == 0) {
        float bm = s_min[0];
        int nw = (blockDim.x + 31) >> 5;
        for (int w = 1; w < nw; w++) bm = fminf(bm, s_min[w]);
        // float atomic-min: disp >= 0 here, but handle sign generically
        if (bm >= 0.0f) {
            atomicMin(&g_min_bits, __float_as_int(bm));
        } else {
            atomicMax((unsigned int*)&g_min_bits, __float_as_uint(bm));
        }
    }
}

// One block per (b, y) row. 1-D splat along x into shared-memory bins.
__global__ __launch_bounds__(256)
void warp_row_kernel(const float* __restrict__ im,
                     const float* __restrict__ disp,
                     float* __restrict__ out_res,
                     float* __restrict__ out_occ) {
    __shared__ float s0[IMG_W];
    __shared__ float s1[IMG_W];
    __shared__ float s2[IMG_W];
    __shared__ float sw[IMG_W];
    __shared__ float so[IMG_W];

    const int row = blockIdx.x;            // b * IMG_H + y
    const int b = row / IMG_H;
    const int y = row - b * IMG_H;

    const float dmin = __int_as_float(g_min_bits);

    const float* drow = disp + (size_t)row * IMG_W;
    const float* im0 = im + (((size_t)b * CHANS + 0) * IMG_H + y) * IMG_W;
    const float* im1 = im + (((size_t)b * CHANS + 1) * IMG_H + y) * IMG_W;
    const float* im2 = im + (((size_t)b * CHANS + 2) * IMG_H + y) * IMG_W;

    for (int i = threadIdx.x; i < IMG_W; i += blockDim.x) {
        s0[i] = 0.0f; s1[i] = 0.0f; s2[i] = 0.0f;
        sw[i] = 0.0f; so[i] = 0.0f;
    }
    __syncthreads();

    for (int col = threadIdx.x; col < IMG_W; col += blockDim.x) {
        float d = drow[col];
        float w = exp2f((d - dmin) * LOG2_WARP_BASE);
        float x = (float)col - d;
        float x0 = floorf(x);
        int xi = (int)x0;
        float wx1 = x - x0;
        float wx0 = 1.0f - wx1;
        float v0 = im0[col] * w;
        float v1 = im1[col] * w;
        float v2 = im2[col] * w;

        if (xi >= 0 && xi < IMG_W) {
            atomicAdd(&s0[xi], v0 * wx0);
            atomicAdd(&s1[xi], v1 * wx0);
            atomicAdd(&s2[xi], v2 * wx0);
            atomicAdd(&sw[xi], w  * wx0);
            atomicAdd(&so[xi], wx0);
        }
        int xj = xi + 1;
        if (xj >= 0 && xj < IMG_W) {
            atomicAdd(&s0[xj], v0 * wx1);
            atomicAdd(&s1[xj], v1 * wx1);
            atomicAdd(&s2[xj], v2 * wx1);
            atomicAdd(&sw[xj], w  * wx1);
            atomicAdd(&so[xj], wx1);
        }
    }
    __syncthreads();

    float* r0 = out_res + (((size_t)b * CHANS + 0) * IMG_H + y) * IMG_W;
    float* r1 = out_res + (((size_t)b * CHANS + 1) * IMG_H + y) * IMG_W;
    float* r2 = out_res + (((size_t)b * CHANS + 2) * IMG_H + y) * IMG_W;
    float* oc = out_occ + (size_t)row * IMG_W;

    for (int i = threadIdx.x; i < IMG_W; i += blockDim.x) {
        float m = fmaxf(sw[i], EPS_F);
        float inv = 1.0f / m;
        r0[i] = s0[i] * inv;
        r1[i] = s1[i] * inv;
        r2[i] = s2[i] * inv;
        oc[i] = 1.0f - __saturatef(so[i]);
    }
}

extern "C" void kernel_launch(void* const* d_in, const int* in_sizes, int n_in,
                              void* d_out, int out_size) {
    const float* im = (const float*)d_in[0];
    const float* disp = (const float*)d_in[1];
    float* out_res = (float*)d_out;
    float* out_occ = (float*)d_out + (size_t)BATCH * CHANS * IMG_H * IMG_W;

    const int n_disp = BATCH * IMG_H * IMG_W;  // 7,372,800
    const int n4 = n_disp / 4;

    init_min_kernel<<<1, 1>>>();
    min_reduce_kernel<<<1184, 256>>>(disp, n4);
    warp_row_kernel<<<BATCH * IMG_H, 256>>>(im, disp, out_res, out_occ);
}

// round 3
// speedup vs baseline: 1.1315x; 1.1315x over previous
#include <cuda_runtime.h>

// Problem shape (fixed by the dataset)
#define BATCH 8
#define CHANS 3
#define IMG_H 720
#define IMG_W 1280
#define EPS_F 1e-6f
// log2(1.414) in double precision
#define LOG2_WARP_BASE 0.49978212546913446f

// Staging transpose: column col lives at (col%40)*33 + col/40  (33 = pad for banks)
#define TPAD 33
#define TSZ  (40 * TPAD)   // 1320

__device__ __forceinline__ float fast_exp2(float x) {
    float r;
    asm("ex2.approx.f32 %0, %1;" : "=f"(r) : "f"(x));
    return r;
}

// One block per (b, y) row. 1-D splat along x into shared-memory bins.
// Lane l owns columns 40*l + (w + 8*i): per-instruction lane target windows are
// disjoint -> no same-address shared-atomic serialization.
__global__ __launch_bounds__(256)
void warp_row_kernel(const float* __restrict__ im,
                     const float* __restrict__ disp,
                     float* __restrict__ out_res,
                     float* __restrict__ out_occ) {
    __shared__ float s0[IMG_W];
    __shared__ float s1[IMG_W];
    __shared__ float s2[IMG_W];
    __shared__ float sm[IMG_W];
    __shared__ float so[IMG_W];
    __shared__ float td[TSZ];
    __shared__ float t0[TSZ];
    __shared__ float t1[TSZ];
    __shared__ float t2[TSZ];

    const int row = blockIdx.x;            // b * IMG_H + y
    const int b = row / IMG_H;
    const int y = row - b * IMG_H;
    const int tid = threadIdx.x;

    const float* drow = disp + (size_t)row * IMG_W;
    const float* im0 = im + (((size_t)b * CHANS + 0) * IMG_H + y) * IMG_W;
    const float* im1 = im + (((size_t)b * CHANS + 1) * IMG_H + y) * IMG_W;
    const float* im2 = im + (((size_t)b * CHANS + 2) * IMG_H + y) * IMG_W;

    // Stage row (coalesced global reads, transposed smem writes) + zero bins.
    #pragma unroll
    for (int k = 0; k < 5; k++) {
        int idx = tid + 256 * k;
        int p = (idx % 40) * TPAD + (idx / 40);
        td[p] = drow[idx];
        t0[p] = im0[idx];
        t1[p] = im1[idx];
        t2[p] = im2[idx];
        s0[idx] = 0.0f; s1[idx] = 0.0f; s2[idx] = 0.0f;
        sm[idx] = 0.0f; so[idx] = 0.0f;
    }
    __syncthreads();

    const int l = tid & 31;        // lane
    const int w = tid >> 5;        // warp in block
    #pragma unroll
    for (int i = 0; i < 5; i++) {
        const int c = w + 8 * i;           // 0..39
        const int p = c * TPAD + l;        // bank-conflict-free across lanes
        const int col = 40 * l + c;

        float d = td[p];
        float wm = fast_exp2(d * (float)LOG2_WARP_BASE);
        float x = (float)col - d;
        float x0f = floorf(x);
        int xi = (int)x0f;
        float wx1 = x - x0f;
        float wx0 = 1.0f - wx1;
        float v0 = t0[p] * wm;
        float v1 = t1[p] * wm;
        float v2 = t2[p] * wm;

        if (xi >= 0) {  // xi <= col < IMG_W always
            atomicAdd(&s0[xi], v0 * wx0);
            atomicAdd(&s1[xi], v1 * wx0);
            atomicAdd(&s2[xi], v2 * wx0);
            atomicAdd(&sm[xi], wm * wx0);
            atomicAdd(&so[xi], wx0);
        }
        int xj = xi + 1;
        if (xj >= 0 && xj < IMG_W) {
            atomicAdd(&s0[xj], v0 * wx1);
            atomicAdd(&s1[xj], v1 * wx1);
            atomicAdd(&s2[xj], v2 * wx1);
            atomicAdd(&sm[xj], wm * wx1);
            atomicAdd(&so[xj], wx1);
        }
    }
    __syncthreads();

    // Epilogue: normalize + occlusion, float4 stores.
    float4* r0 = (float4*)(out_res + (((size_t)b * CHANS + 0) * IMG_H + y) * IMG_W);
    float4* r1 = (float4*)(out_res + (((size_t)b * CHANS + 1) * IMG_H + y) * IMG_W);
    float4* r2 = (float4*)(out_res + (((size_t)b * CHANS + 2) * IMG_H + y) * IMG_W);
    float4* oc = (float4*)(out_occ + (size_t)row * IMG_W);
    const float4* b0 = (const float4*)s0;
    const float4* b1 = (const float4*)s1;
    const float4* b2 = (const float4*)s2;
    const float4* bm = (const float4*)sm;
    const float4* bo = (const float4*)so;

    for (int idx = tid; idx < IMG_W / 4; idx += 256) {
        float4 m4 = bm[idx];
        float4 i0 = b0[idx];
        float4 i1 = b1[idx];
        float4 i2 = b2[idx];
        float4 o4 = bo[idx];
        float inx = 1.0f / fmaxf(m4.x, EPS_F);
        float iny = 1.0f / fmaxf(m4.y, EPS_F);
        float inz = 1.0f / fmaxf(m4.z, EPS_F);
        float inw = 1.0f / fmaxf(m4.w, EPS_F);
        r0[idx] = make_float4(i0.x * inx, i0.y * iny, i0.z * inz, i0.w * inw);
        r1[idx] = make_float4(i1.x * inx, i1.y * iny, i1.z * inz, i1.w * inw);
        r2[idx] = make_float4(i2.x * inx, i2.y * iny, i2.z * inz, i2.w * inw);
        oc[idx] = make_float4(1.0f - __saturatef(o4.x), 1.0f - __saturatef(o4.y),
                              1.0f - __saturatef(o4.z), 1.0f - __saturatef(o4.w));
    }
}

extern "C" void kernel_launch(void* const* d_in, const int* in_sizes, int n_in,
                              void* d_out, int out_size) {
    const float* im = (const float*)d_in[0];
    const float* disp = (const float*)d_in[1];
    float* out_res = (float*)d_out;
    float* out_occ = (float*)d_out + (size_t)BATCH * CHANS * IMG_H * IMG_W;

    warp_row_kernel<<<BATCH * IMG_H, 256>>>(im, disp, out_res, out_occ);
}